// round 15
// baseline (speedup 1.0000x reference)
#include <cuda_runtime.h>
#include <cuda_fp16.h>
#include <cstdint>

// ---------------- problem constants ----------------
#define BQ      16384
#define NCQ     13
#define FQ      26
#define VQ      100000
#define DQ      16
#define HQ      400       // H1 == H2
#define DNN_INQ 429
#define KP      448       // padded K (14 * 32)
#define NPAD    448       // padded N (7 * 64)

// GEMM tiling: BM=128, BN=64, BK=32; 8 warps, warp tile 32x32 (4 M x 2 N)
#define BM 128
#define BN 64
#define BK 32
#define NIT (KP / BK)     // 14
#define AST 80            // smem row stride bytes (64B data + 16B pad)

// smem stage layout (bytes): A_hi | A_lo | B  (B single fp16)
#define A_HI_OFF 0
#define A_LO_OFF 10240    // 128 * 80
#define B_OFF    20480    // 64 * 80 = 5120
#define STAGE    25600
#define NSTAGE   2
#define SMEM_TOTAL (NSTAGE * STAGE)   // 51200 -> 4 CTAs/SM (204.8KB)

// ---------------- scratch (static device globals) ----------------
__device__ __align__(16) __half g_dnn_hi[BQ * KP];
__device__ __align__(16) __half g_dnn_lo[BQ * KP];
__device__ __align__(16) __half g_h1_hi [BQ * KP];
__device__ __align__(16) __half g_h1_lo [BQ * KP];
__device__ __align__(16) __half g_w1t   [NPAD * KP];
__device__ __align__(16) __half g_w2t   [NPAD * KP];

// ---------------- PTX helpers ----------------
__device__ __forceinline__ uint32_t smem_u32_of(const void* p) {
    uint32_t a;
    asm("{ .reg .u64 t; cvta.to.shared.u64 t, %1; cvt.u32.u64 %0, t; }" : "=r"(a) : "l"(p));
    return a;
}

#define LDMATRIX_X4(r, addr) \
    asm volatile("ldmatrix.sync.aligned.m8n8.x4.shared.b16 {%0,%1,%2,%3}, [%4];" \
                 : "=r"((r)[0]), "=r"((r)[1]), "=r"((r)[2]), "=r"((r)[3]) \
                 : "r"(addr))

#define MMA16816H(d, a, b0, b1) \
    asm volatile("mma.sync.aligned.m16n8k16.row.col.f32.f16.f16.f32 " \
                 "{%0,%1,%2,%3}, {%4,%5,%6,%7}, {%8,%9}, {%0,%1,%2,%3};" \
                 : "+f"((d)[0]), "+f"((d)[1]), "+f"((d)[2]), "+f"((d)[3]) \
                 : "r"((a)[0]), "r"((a)[1]), "r"((a)[2]), "r"((a)[3]), \
                   "r"(b0), "r"(b1))

#define CP_ASYNC16(smem_addr, gptr) \
    asm volatile("cp.async.cg.shared.global [%0], [%1], 16;" \
                 :: "r"(smem_addr), "l"(gptr))
#define CP_COMMIT()  asm volatile("cp.async.commit_group;" ::: "memory")
#define CP_WAIT(N)   asm volatile("cp.async.wait_group %0;" :: "n"(N) : "memory")

// ---------------------------------------------------------------------------
// Kernel 1: embedding gather + FM + build dnn_in (fp16 hi/lo) + init out
// Half-warp (16 lanes) per row.
// ---------------------------------------------------------------------------
__global__ void gather_fm_kernel(const float* __restrict__ cont,
                                 const int*   __restrict__ cat,
                                 const float* __restrict__ Wc,
                                 const float* __restrict__ bc,
                                 const float* __restrict__ emb1,
                                 const float* __restrict__ emb,
                                 const float* __restrict__ Wout,
                                 const float* __restrict__ bout,
                                 float* __restrict__ out)
{
    int lane = threadIdx.x;
    int sl   = lane & 15;
    int row  = blockIdx.x * (blockDim.y * 2) + threadIdx.y * 2 + (lane >> 4);
    if (row >= BQ) return;

    const int* idx = cat + row * FQ;
    unsigned base = (unsigned)row * KP;
    float acc = 0.f;

    {
        float s = 0.f, ss = 0.f;
        #pragma unroll
        for (int f = 0; f < FQ; f++) {
            int id  = idx[f];
            float e = emb[((long)f * VQ + id) * DQ + sl];
            __half hi = __float2half_rn(e);
            float lo = e - __half2float(hi);
            int col = NCQ + f * DQ + sl;
            g_dnn_hi[base + col] = hi;
            g_dnn_lo[base + col] = __float2half_rn(lo);
            s  += e;
            ss += e * e;
        }
        acc += 0.5f * (s * s - ss);
    }
    acc += emb1[(long)sl * VQ + idx[sl]];
    if (sl < FQ - 16)
        acc += emb1[(long)(sl + 16) * VQ + idx[sl + 16]];
    if (sl < NCQ) {
        float c = cont[row * NCQ + sl];
        __half hi = __float2half_rn(c);
        float lo = c - __half2float(hi);
        g_dnn_hi[base + sl] = hi;
        g_dnn_lo[base + sl] = __float2half_rn(lo);
        acc += c * Wc[sl];
    }
    {   // pad cols 429..447
        int pc = DNN_INQ + sl;
        g_dnn_hi[base + pc] = __float2half_rn(0.f);
        g_dnn_lo[base + pc] = __float2half_rn(0.f);
        if (sl < 3) {
            g_dnn_hi[base + pc + 16] = __float2half_rn(0.f);
            g_dnn_lo[base + pc + 16] = __float2half_rn(0.f);
        }
    }

    #pragma unroll
    for (int o = 8; o > 0; o >>= 1)
        acc += __shfl_down_sync(0xffffffffu, acc, o, 16);
    if (sl == 0)
        out[row] = (acc + bc[0]) * Wout[0] + bout[0];
}

// ---------------------------------------------------------------------------
// Prep: transpose + pad W [K][N] fp32 -> Wt [NPAD][KP] fp16 (single)
// ---------------------------------------------------------------------------
__global__ void prep_w_kernel(const float* __restrict__ W,
                              __half* __restrict__ Wt,
                              int K, int N)
{
    int idx = blockIdx.x * blockDim.x + threadIdx.x;
    if (idx >= NPAD * KP) return;
    int n = idx / KP, k = idx % KP;
    float v = (k < K && n < N) ? W[(long)k * N + n] : 0.f;
    Wt[idx] = __float2half_rn(v);
}

// ---------------------------------------------------------------------------
// fp16x2 HMMA GEMM, cp.async 2-stage, load-before-compute:
//   wait(0) -> sync -> issue load(it+1) -> compute(it)
// mode 0: write fp16 hi/lo (stride KP) -> h1
// mode 1: fused final GEMV into out
// ---------------------------------------------------------------------------
__global__ __launch_bounds__(256, 4)
void gemm_mma_kernel(const __half* __restrict__ Ah,
                     const __half* __restrict__ Al,
                     const __half* __restrict__ B,
                     const float* __restrict__ bias, int mode,
                     __half* __restrict__ Ch,
                     __half* __restrict__ Cl,
                     const float* __restrict__ Wout,
                     float* __restrict__ out)
{
    extern __shared__ __align__(128) char smem[];
    const uint32_t smem_b = smem_u32_of(smem);

    const int tid  = threadIdx.x;
    const int wid  = tid >> 5;
    const int lane = tid & 31;
    const int wm   = wid >> 1;      // 4 warps along M (32 rows each)
    const int wn   = wid & 1;       // 2 warps along N (32 cols each)

    const int row0 = blockIdx.y * BM;
    const int n0   = blockIdx.x * BN;

    // cp.async coords: r = tid>>2 (64 rows/round), c = tid&3 (4 x 16B = 64B row)
    const int cr = tid >> 2, cc = tid & 3;

    // per-thread base pointers (32-bit offsets into <15MB scratch arrays)
    const char* pA0h = (const char*)Ah + ((unsigned)(row0 + cr) * KP * 2u + cc * 16u);
    const char* pA0l = (const char*)Al + ((unsigned)(row0 + cr) * KP * 2u + cc * 16u);
    const char* pB0  = (const char*)B  + ((unsigned)(n0   + cr) * KP * 2u + cc * 16u);
    const uint32_t sA = smem_b + A_HI_OFF + cr * AST + cc * 16;
    const uint32_t sB = smem_b + B_OFF    + cr * AST + cc * 16;

    auto load_stage = [&](int slot, int it) {
        const uint32_t so = slot * STAGE;
        const unsigned kb = (unsigned)it * (BK * 2);
        #pragma unroll
        for (int i = 0; i < 2; i++) {
            CP_ASYNC16(sA + so + i * (64 * AST),                 pA0h + kb + i * (64u * KP * 2));
            CP_ASYNC16(sA + so + i * (64 * AST) + (A_LO_OFF - A_HI_OFF),
                                                                 pA0l + kb + i * (64u * KP * 2));
        }
        CP_ASYNC16(sB + so, pB0 + kb);
    };

    float acc[2][4][4];
    #pragma unroll
    for (int i = 0; i < 2; i++)
        #pragma unroll
        for (int j = 0; j < 4; j++)
            #pragma unroll
            for (int q = 0; q < 4; q++) acc[i][j][q] = 0.f;

    const uint32_t halfoff = ((lane >> 4) & 1) * 16;
    const uint32_t aBase = smem_b + A_HI_OFF + (wm * 32 + (lane & 15)) * AST + halfoff;
    const uint32_t bBase = smem_b + B_OFF + (wn * 32 + (lane & 15)) * AST + halfoff;

    load_stage(0, 0); CP_COMMIT();

    int cur = 0;
    for (int it = 0; it < NIT; ++it) {
        CP_WAIT(0);           // data for iter `it` landed (issued >=1 compute ago)
        __syncthreads();

        if (it + 1 < NIT) { load_stage(cur ^ 1, it + 1); CP_COMMIT(); }

        const uint32_t so = cur * STAGE;
        #pragma unroll
        for (int kq = 0; kq < 2; kq++) {
            const uint32_t koff = so + kq * 32;
            uint32_t ah[2][4], al[2][4], bh[2][4];
            #pragma unroll
            for (int g = 0; g < 2; g++)
                LDMATRIX_X4(bh[g], bBase + koff + g * (16 * AST));
            #pragma unroll
            for (int mt = 0; mt < 2; mt++) {
                LDMATRIX_X4(ah[mt], aBase + koff + mt * (16 * AST));
                LDMATRIX_X4(al[mt], aBase + koff + mt * (16 * AST) + (A_LO_OFF - A_HI_OFF));
            }
            #pragma unroll
            for (int mt = 0; mt < 2; mt++) {
                #pragma unroll
                for (int g = 0; g < 2; g++) {
                    #pragma unroll
                    for (int s = 0; s < 2; s++) {
                        float* d = acc[mt][g * 2 + s];
                        MMA16816H(d, ah[mt], bh[g][s], bh[g][s + 2]);
                        MMA16816H(d, al[mt], bh[g][s], bh[g][s + 2]);
                    }
                }
            }
        }

        cur ^= 1;
    }

    // ---- epilogue ----
    if (mode == 0) {
        #pragma unroll
        for (int mt = 0; mt < 2; mt++) {
            #pragma unroll
            for (int nt = 0; nt < 4; nt++) {
                const float* d = acc[mt][nt];
                unsigned gr = (unsigned)row0 + wm * 32 + mt * 16 + (lane >> 2);
                int gcol = n0 + wn * 32 + nt * 8 + (lane & 3) * 2;
                float b0 = (gcol < HQ)     ? bias[gcol]     : 0.f;
                float b1 = (gcol + 1 < HQ) ? bias[gcol + 1] : 0.f;
                float v00 = fmaxf(d[0] + b0, 0.f), v01 = fmaxf(d[1] + b1, 0.f);
                float v10 = fmaxf(d[2] + b0, 0.f), v11 = fmaxf(d[3] + b1, 0.f);
                __half2 h0 = __floats2half2_rn(v00, v01);
                __half2 h1v = __floats2half2_rn(v10, v11);
                __half2 l0 = __floats2half2_rn(v00 - __half2float(__low2half(h0)),
                                               v01 - __half2float(__high2half(h0)));
                __half2 l1 = __floats2half2_rn(v10 - __half2float(__low2half(h1v)),
                                               v11 - __half2float(__high2half(h1v)));
                *(__half2*)&Ch[gr * KP + gcol]       = h0;
                *(__half2*)&Cl[gr * KP + gcol]       = l0;
                *(__half2*)&Ch[(gr + 8) * KP + gcol] = h1v;
                *(__half2*)&Cl[(gr + 8) * KP + gcol] = l1;
            }
        }
    } else {
        // reuse stage-0 smem as the row-reduction buffer (pipeline is done)
        float* red = (float*)smem;
        __syncthreads();
        if (tid < BM) red[tid] = 0.f;
        __syncthreads();
        #pragma unroll
        for (int mt = 0; mt < 2; mt++) {
            float p0 = 0.f, p1 = 0.f;
            #pragma unroll
            for (int nt = 0; nt < 4; nt++) {
                const float* d = acc[mt][nt];
                int gcol = n0 + wn * 32 + nt * 8 + (lane & 3) * 2;
                float w0 = (gcol < HQ)     ? Wout[1 + gcol] : 0.f;
                float w1 = (gcol + 1 < HQ) ? Wout[2 + gcol] : 0.f;
                float b0 = (gcol < HQ)     ? bias[gcol]     : 0.f;
                float b1 = (gcol + 1 < HQ) ? bias[gcol + 1] : 0.f;
                p0 += fmaxf(d[0] + b0, 0.f) * w0 + fmaxf(d[1] + b1, 0.f) * w1;
                p1 += fmaxf(d[2] + b0, 0.f) * w0 + fmaxf(d[3] + b1, 0.f) * w1;
            }
            p0 += __shfl_xor_sync(0xffffffffu, p0, 1);
            p0 += __shfl_xor_sync(0xffffffffu, p0, 2);
            p1 += __shfl_xor_sync(0xffffffffu, p1, 1);
            p1 += __shfl_xor_sync(0xffffffffu, p1, 2);
            if ((lane & 3) == 0) {
                int lr = wm * 32 + mt * 16 + (lane >> 2);
                atomicAdd(&red[lr],     p0);
                atomicAdd(&red[lr + 8], p1);
            }
        }
        __syncthreads();
        if (tid < BM)
            atomicAdd(&out[row0 + tid], red[tid]);
    }
}

// ---------------------------------------------------------------------------
// Launch
// ---------------------------------------------------------------------------
extern "C" void kernel_launch(void* const* d_in, const int* in_sizes, int n_in,
                              void* d_out, int out_size)
{
    const float* cont = (const float*)d_in[0];
    const int*   cat  = (const int*)  d_in[1];
    const float* Wc   = (const float*)d_in[2];
    const float* bc   = (const float*)d_in[3];
    const float* emb1 = (const float*)d_in[4];
    const float* emb  = (const float*)d_in[5];
    const float* W1   = (const float*)d_in[6];
    const float* b1   = (const float*)d_in[7];
    const float* W2   = (const float*)d_in[8];
    const float* b2   = (const float*)d_in[9];
    const float* Wout = (const float*)d_in[10];
    const float* bout = (const float*)d_in[11];
    float* out = (float*)d_out;

    void *p;
    cudaGetSymbolAddress(&p, g_dnn_hi); __half* dnn_hi = (__half*)p;
    cudaGetSymbolAddress(&p, g_dnn_lo); __half* dnn_lo = (__half*)p;
    cudaGetSymbolAddress(&p, g_h1_hi);  __half* h1_hi  = (__half*)p;
    cudaGetSymbolAddress(&p, g_h1_lo);  __half* h1_lo  = (__half*)p;
    cudaGetSymbolAddress(&p, g_w1t);    __half* w1t    = (__half*)p;
    cudaGetSymbolAddress(&p, g_w2t);    __half* w2t    = (__half*)p;

    static bool attr_set = false;
    if (!attr_set) {
        cudaFuncSetAttribute(gemm_mma_kernel,
                             cudaFuncAttributeMaxDynamicSharedMemorySize, SMEM_TOTAL);
        attr_set = true;
    }

    // weight prep (tiny)
    {
        int total = NPAD * KP;
        prep_w_kernel<<<(total + 255) / 256, 256>>>(W1, w1t, DNN_INQ, HQ);
        prep_w_kernel<<<(total + 255) / 256, 256>>>(W2, w2t, HQ, HQ);
    }
    // gather + FM + dnn_in + out init
    {
        dim3 blk(32, 8);
        gather_fm_kernel<<<BQ / 16, blk>>>(cont, cat, Wc, bc, emb1, emb,
                                           Wout, bout, out);
    }
    // h1 = relu(dnn @ W1 + b1)
    {
        dim3 grd(NPAD / BN, BQ / BM);   // (7, 128)
        gemm_mma_kernel<<<grd, 256, SMEM_TOTAL>>>(dnn_hi, dnn_lo, w1t, b1, 0,
                                                  h1_hi, h1_lo, nullptr, nullptr);
    }
    // h2 = relu(h1 @ W2 + b2), fused with final GEMV into out
    {
        dim3 grd(NPAD / BN, BQ / BM);
        gemm_mma_kernel<<<grd, 256, SMEM_TOTAL>>>(h1_hi, h1_lo, w2t, b2, 1,
                                                  nullptr, nullptr, Wout, out);
    }
}

// round 16
// speedup vs baseline: 1.6137x; 1.6137x over previous
#include <cuda_runtime.h>
#include <cuda_fp16.h>
#include <cstdint>

// ---------------- problem constants ----------------
#define BQ      16384
#define NCQ     13
#define FQ      26
#define VQ      100000
#define DQ      16
#define HQ      400       // H1 == H2
#define DNN_INQ 429
#define KP      448       // padded K (14 * 32)
#define NPAD    448       // padded N (7 * 64)

// GEMM tiling: BM=64, BN=448 (full weight cols), BK=32; 8 warps, warp 32x112
#define BM 64
#define BN 448
#define BK 32
#define NIT (KP / BK)     // 14

// smem stage layout (bytes), zero-pad XOR-swizzled 64B rows:
//   A_hi 64*64=4096 | A_lo 4096 | B 448*64=28672
#define A_HI_OFF 0
#define A_LO_OFF 4096
#define B_OFF    8192
#define STAGE    36864
#define NSTAGE   3
#define SMEM_TOTAL (NSTAGE * STAGE)   // 110592 -> 2 CTAs/SM

// ---------------- scratch (static device globals) ----------------
__device__ __align__(16) __half g_dnn_hi[BQ * KP];
__device__ __align__(16) __half g_dnn_lo[BQ * KP];
__device__ __align__(16) __half g_h1_hi [BQ * KP];
__device__ __align__(16) __half g_h1_lo [BQ * KP];
__device__ __align__(16) __half g_w1t   [NPAD * KP];
__device__ __align__(16) __half g_w2t   [NPAD * KP];

// ---------------- PTX helpers ----------------
__device__ __forceinline__ uint32_t smem_u32_of(const void* p) {
    uint32_t a;
    asm("{ .reg .u64 t; cvta.to.shared.u64 t, %1; cvt.u32.u64 %0, t; }" : "=r"(a) : "l"(p));
    return a;
}

// swizzled byte offset of 16B chunk c (0..3) of 64B row r; conflict-free for
// any 8 consecutive rows: slot = ((r&1)*4+c) ^ ((r>>1)&3) within 128B pair.
__device__ __forceinline__ uint32_t swz(uint32_t r, uint32_t c) {
    return (r >> 1) * 128u + ((((r & 1u) << 2) | c) ^ ((r >> 1) & 3u)) * 16u;
}

#define LDMATRIX_X4(r, addr) \
    asm volatile("ldmatrix.sync.aligned.m8n8.x4.shared.b16 {%0,%1,%2,%3}, [%4];" \
                 : "=r"((r)[0]), "=r"((r)[1]), "=r"((r)[2]), "=r"((r)[3]) \
                 : "r"(addr))

#define MMA16816H(d, a, b0, b1) \
    asm volatile("mma.sync.aligned.m16n8k16.row.col.f32.f16.f16.f32 " \
                 "{%0,%1,%2,%3}, {%4,%5,%6,%7}, {%8,%9}, {%0,%1,%2,%3};" \
                 : "+f"((d)[0]), "+f"((d)[1]), "+f"((d)[2]), "+f"((d)[3]) \
                 : "r"((a)[0]), "r"((a)[1]), "r"((a)[2]), "r"((a)[3]), \
                   "r"(b0), "r"(b1))

#define CP_ASYNC16(smem_addr, gptr) \
    asm volatile("cp.async.cg.shared.global [%0], [%1], 16;" \
                 :: "r"(smem_addr), "l"(gptr))
#define CP_COMMIT()  asm volatile("cp.async.commit_group;" ::: "memory")
#define CP_WAIT(N)   asm volatile("cp.async.wait_group %0;" :: "n"(N) : "memory")

// ---------------------------------------------------------------------------
// Kernel 1: embedding gather + FM + build dnn_in (fp16 hi/lo) + init out
// Half-warp (16 lanes) per row.
// ---------------------------------------------------------------------------
__global__ void gather_fm_kernel(const float* __restrict__ cont,
                                 const int*   __restrict__ cat,
                                 const float* __restrict__ Wc,
                                 const float* __restrict__ bc,
                                 const float* __restrict__ emb1,
                                 const float* __restrict__ emb,
                                 const float* __restrict__ Wout,
                                 const float* __restrict__ bout,
                                 float* __restrict__ out)
{
    int lane = threadIdx.x;
    int sl   = lane & 15;
    int row  = blockIdx.x * (blockDim.y * 2) + threadIdx.y * 2 + (lane >> 4);
    if (row >= BQ) return;

    const int* idx = cat + row * FQ;
    unsigned base = (unsigned)row * KP;
    float acc = 0.f;

    {
        float s = 0.f, ss = 0.f;
        #pragma unroll
        for (int f = 0; f < FQ; f++) {
            int id  = idx[f];
            float e = emb[((long)f * VQ + id) * DQ + sl];
            __half hi = __float2half_rn(e);
            float lo = e - __half2float(hi);
            int col = NCQ + f * DQ + sl;
            g_dnn_hi[base + col] = hi;
            g_dnn_lo[base + col] = __float2half_rn(lo);
            s  += e;
            ss += e * e;
        }
        acc += 0.5f * (s * s - ss);
    }
    acc += emb1[(long)sl * VQ + idx[sl]];
    if (sl < FQ - 16)
        acc += emb1[(long)(sl + 16) * VQ + idx[sl + 16]];
    if (sl < NCQ) {
        float c = cont[row * NCQ + sl];
        __half hi = __float2half_rn(c);
        float lo = c - __half2float(hi);
        g_dnn_hi[base + sl] = hi;
        g_dnn_lo[base + sl] = __float2half_rn(lo);
        acc += c * Wc[sl];
    }
    {   // pad cols 429..447
        int pc = DNN_INQ + sl;
        g_dnn_hi[base + pc] = __float2half_rn(0.f);
        g_dnn_lo[base + pc] = __float2half_rn(0.f);
        if (sl < 3) {
            g_dnn_hi[base + pc + 16] = __float2half_rn(0.f);
            g_dnn_lo[base + pc + 16] = __float2half_rn(0.f);
        }
    }

    #pragma unroll
    for (int o = 8; o > 0; o >>= 1)
        acc += __shfl_down_sync(0xffffffffu, acc, o, 16);
    if (sl == 0)
        out[row] = (acc + bc[0]) * Wout[0] + bout[0];
}

// ---------------------------------------------------------------------------
// Prep: transpose + pad W [K][N] fp32 -> Wt [NPAD][KP] fp16 (single)
// ---------------------------------------------------------------------------
__global__ void prep_w_kernel(const float* __restrict__ W,
                              __half* __restrict__ Wt,
                              int K, int N)
{
    int idx = blockIdx.x * blockDim.x + threadIdx.x;
    if (idx >= NPAD * KP) return;
    int n = idx / KP, k = idx % KP;
    float v = (k < K && n < N) ? W[(long)k * N + n] : 0.f;
    Wt[idx] = __float2half_rn(v);
}

// ---------------------------------------------------------------------------
// fp16x2 HMMA GEMM, BM=64 x BN=448 (all weight cols per CTA), 3-stage depth-2:
//   wait(1) -> sync -> issue load(it+2) -> compute(it)     [R13 pipeline]
// mode 0: write fp16 hi/lo (stride KP) -> h1
// mode 1: fused final GEMV: out[row] += sum_col relu(.)*Wout[1+col]  (no atomics)
// ---------------------------------------------------------------------------
__global__ __launch_bounds__(256)
void gemm_mma_kernel(const __half* __restrict__ Ah,
                     const __half* __restrict__ Al,
                     const __half* __restrict__ B,
                     const float* __restrict__ bias, int mode,
                     __half* __restrict__ Ch,
                     __half* __restrict__ Cl,
                     const float* __restrict__ Wout,
                     float* __restrict__ out)
{
    extern __shared__ __align__(128) char smem[];
    const uint32_t smem_b = smem_u32_of(smem);

    const int tid  = threadIdx.x;
    const int wid  = tid >> 5;
    const int lane = tid & 31;
    const int wm   = wid >> 2;      // 2 warps along M (32 rows each)
    const int wn   = wid & 3;       // 4 warps along N (112 cols each)

    const int row0 = blockIdx.x * BM;

    // cp.async coords: r = tid>>2, c = tid&3 (4 x 16B per 64B row)
    const int cr = tid >> 2, cc = tid & 3;

    const char* pAh = (const char*)Ah + ((unsigned)(row0 + cr) * (KP * 2u) + cc * 16u);
    const char* pAl = (const char*)Al + ((unsigned)(row0 + cr) * (KP * 2u) + cc * 16u);
    const char* pB  = (const char*)B;

    const uint32_t swzA = swz(cr, cc);
    uint32_t swzB[7];
    #pragma unroll
    for (int i = 0; i < 7; i++) swzB[i] = swz(cr + i * 64, cc);

    auto load_stage = [&](int slot, int it) {
        const uint32_t so = smem_b + slot * STAGE;
        const unsigned kb = (unsigned)it * (BK * 2);
        CP_ASYNC16(so + A_HI_OFF + swzA, pAh + kb);
        CP_ASYNC16(so + A_LO_OFF + swzA, pAl + kb);
        #pragma unroll
        for (int i = 0; i < 7; i++) {
            unsigned r = (unsigned)(cr + i * 64);
            CP_ASYNC16(so + B_OFF + swzB[i], pB + r * (KP * 2u) + kb + cc * 16u);
        }
    };

    // ldmatrix swizzled offsets (relative to stage base)
    const int hoff = (lane >> 4) & 1;
    uint32_t offA[2][2], offB7[7][2];
    #pragma unroll
    for (int mt = 0; mt < 2; mt++)
        #pragma unroll
        for (int kq = 0; kq < 2; kq++)
            offA[mt][kq] = A_HI_OFF + swz(wm * 32 + mt * 16 + (lane & 15), kq * 2 + hoff);
    #pragma unroll
    for (int nt = 0; nt < 7; nt++)
        #pragma unroll
        for (int kq = 0; kq < 2; kq++)
            offB7[nt][kq] = B_OFF + swz(wn * 112 + nt * 16 + (lane & 15), kq * 2 + hoff);

    float acc[2][14][4];
    #pragma unroll
    for (int i = 0; i < 2; i++)
        #pragma unroll
        for (int j = 0; j < 14; j++)
            #pragma unroll
            for (int q = 0; q < 4; q++) acc[i][j][q] = 0.f;

    // depth-2 prologue
    load_stage(0, 0); CP_COMMIT();
    load_stage(1, 1); CP_COMMIT();

    int cur = 0;
    for (int it = 0; it < NIT; ++it) {
        CP_WAIT(1);
        __syncthreads();

        int nslot = cur + 2; if (nslot >= NSTAGE) nslot -= NSTAGE;
        if (it + 2 < NIT) load_stage(nslot, it + 2);
        CP_COMMIT();

        const uint32_t sbase = smem_b + cur * STAGE;
        #pragma unroll
        for (int kq = 0; kq < 2; kq++) {
            uint32_t ah[2][4], al[2][4];
            #pragma unroll
            for (int mt = 0; mt < 2; mt++) {
                LDMATRIX_X4(ah[mt], sbase + offA[mt][kq]);
                LDMATRIX_X4(al[mt], sbase + offA[mt][kq] + (A_LO_OFF - A_HI_OFF));
            }
            #pragma unroll
            for (int nt = 0; nt < 7; nt++) {
                uint32_t bb[4];
                LDMATRIX_X4(bb, sbase + offB7[nt][kq]);
                #pragma unroll
                for (int mt = 0; mt < 2; mt++) {
                    #pragma unroll
                    for (int s = 0; s < 2; s++) {
                        float* d = acc[mt][nt * 2 + s];
                        MMA16816H(d, ah[mt], bb[s], bb[s + 2]);
                        MMA16816H(d, al[mt], bb[s], bb[s + 2]);
                    }
                }
            }
        }

        cur = cur + 1 == NSTAGE ? 0 : cur + 1;
    }

    // ---- epilogue ----
    if (mode == 0) {
        #pragma unroll
        for (int mt = 0; mt < 2; mt++) {
            unsigned gr = (unsigned)row0 + wm * 32 + mt * 16 + (lane >> 2);
            #pragma unroll
            for (int j = 0; j < 14; j++) {
                const float* d = acc[mt][j];
                int gcol = wn * 112 + j * 8 + (lane & 3) * 2;
                float b0 = (gcol < HQ)     ? bias[gcol]     : 0.f;
                float b1 = (gcol + 1 < HQ) ? bias[gcol + 1] : 0.f;
                float v00 = fmaxf(d[0] + b0, 0.f), v01 = fmaxf(d[1] + b1, 0.f);
                float v10 = fmaxf(d[2] + b0, 0.f), v11 = fmaxf(d[3] + b1, 0.f);
                __half2 h0 = __floats2half2_rn(v00, v01);
                __half2 h1v = __floats2half2_rn(v10, v11);
                __half2 l0 = __floats2half2_rn(v00 - __half2float(__low2half(h0)),
                                               v01 - __half2float(__high2half(h0)));
                __half2 l1 = __floats2half2_rn(v10 - __half2float(__low2half(h1v)),
                                               v11 - __half2float(__high2half(h1v)));
                *(__half2*)&Ch[gr * KP + gcol]       = h0;
                *(__half2*)&Cl[gr * KP + gcol]       = l0;
                *(__half2*)&Ch[(gr + 8) * KP + gcol] = h1v;
                *(__half2*)&Cl[(gr + 8) * KP + gcol] = l1;
            }
        }
    } else {
        // CTA covers ALL cols of its 64 rows -> plain add into out, no atomics
        float* red = (float*)smem;   // reuse stage 0 (mainloop finished)
        __syncthreads();
        if (tid < BM) red[tid] = 0.f;
        __syncthreads();
        #pragma unroll
        for (int mt = 0; mt < 2; mt++) {
            float p0 = 0.f, p1 = 0.f;
            #pragma unroll
            for (int j = 0; j < 14; j++) {
                const float* d = acc[mt][j];
                int gcol = wn * 112 + j * 8 + (lane & 3) * 2;
                float w0 = (gcol < HQ)     ? Wout[1 + gcol] : 0.f;
                float w1 = (gcol + 1 < HQ) ? Wout[2 + gcol] : 0.f;
                float b0 = (gcol < HQ)     ? bias[gcol]     : 0.f;
                float b1 = (gcol + 1 < HQ) ? bias[gcol + 1] : 0.f;
                p0 += fmaxf(d[0] + b0, 0.f) * w0 + fmaxf(d[1] + b1, 0.f) * w1;
                p1 += fmaxf(d[2] + b0, 0.f) * w0 + fmaxf(d[3] + b1, 0.f) * w1;
            }
            p0 += __shfl_xor_sync(0xffffffffu, p0, 1);
            p0 += __shfl_xor_sync(0xffffffffu, p0, 2);
            p1 += __shfl_xor_sync(0xffffffffu, p1, 1);
            p1 += __shfl_xor_sync(0xffffffffu, p1, 2);
            if ((lane & 3) == 0) {
                int lr = wm * 32 + mt * 16 + (lane >> 2);
                atomicAdd(&red[lr],     p0);   // smem atomics, 4 N-warps combine
                atomicAdd(&red[lr + 8], p1);
            }
        }
        __syncthreads();
        if (tid < BM)
            out[row0 + tid] += red[tid];
    }
}

// ---------------------------------------------------------------------------
// Launch
// ---------------------------------------------------------------------------
extern "C" void kernel_launch(void* const* d_in, const int* in_sizes, int n_in,
                              void* d_out, int out_size)
{
    const float* cont = (const float*)d_in[0];
    const int*   cat  = (const int*)  d_in[1];
    const float* Wc   = (const float*)d_in[2];
    const float* bc   = (const float*)d_in[3];
    const float* emb1 = (const float*)d_in[4];
    const float* emb  = (const float*)d_in[5];
    const float* W1   = (const float*)d_in[6];
    const float* b1   = (const float*)d_in[7];
    const float* W2   = (const float*)d_in[8];
    const float* b2   = (const float*)d_in[9];
    const float* Wout = (const float*)d_in[10];
    const float* bout = (const float*)d_in[11];
    float* out = (float*)d_out;

    void *p;
    cudaGetSymbolAddress(&p, g_dnn_hi); __half* dnn_hi = (__half*)p;
    cudaGetSymbolAddress(&p, g_dnn_lo); __half* dnn_lo = (__half*)p;
    cudaGetSymbolAddress(&p, g_h1_hi);  __half* h1_hi  = (__half*)p;
    cudaGetSymbolAddress(&p, g_h1_lo);  __half* h1_lo  = (__half*)p;
    cudaGetSymbolAddress(&p, g_w1t);    __half* w1t    = (__half*)p;
    cudaGetSymbolAddress(&p, g_w2t);    __half* w2t    = (__half*)p;

    static bool attr_set = false;
    if (!attr_set) {
        cudaFuncSetAttribute(gemm_mma_kernel,
                             cudaFuncAttributeMaxDynamicSharedMemorySize, SMEM_TOTAL);
        attr_set = true;
    }

    // weight prep (tiny)
    {
        int total = NPAD * KP;
        prep_w_kernel<<<(total + 255) / 256, 256>>>(W1, w1t, DNN_INQ, HQ);
        prep_w_kernel<<<(total + 255) / 256, 256>>>(W2, w2t, HQ, HQ);
    }
    // gather + FM + dnn_in + out init
    {
        dim3 blk(32, 8);
        gather_fm_kernel<<<BQ / 16, blk>>>(cont, cat, Wc, bc, emb1, emb,
                                           Wout, bout, out);
    }
    // h1 = relu(dnn @ W1 + b1)
    gemm_mma_kernel<<<BQ / BM, 256, SMEM_TOTAL>>>(dnn_hi, dnn_lo, w1t, b1, 0,
                                                  h1_hi, h1_lo, nullptr, nullptr);
    // h2 = relu(h1 @ W2 + b2), fused with final GEMV into out
    gemm_mma_kernel<<<BQ / BM, 256, SMEM_TOTAL>>>(h1_hi, h1_lo, w2t, b2, 1,
                                                  nullptr, nullptr, Wout, out);
}